// round 5
// baseline (speedup 1.0000x reference)
#include <cuda_runtime.h>
#include <cuda_bf16.h>
#include <cstdint>

#define DIM 4096
constexpr float SM_SCALE = 0.015625f;  // 1/sqrt(4096)
#define ELEMS ((size_t)DIM * (size_t)DIM)

// ---------------------------------------------------------------------------
// Scratch (__device__ globals; alloc-free rule).
// ---------------------------------------------------------------------------
__device__ __align__(1024) __nv_bfloat16 g_x_hi[ELEMS];
__device__ __align__(1024) __nv_bfloat16 g_x_lo[ELEMS];
__device__ __align__(1024) __nv_bfloat16 g_wqt_hi[ELEMS];
__device__ __align__(1024) __nv_bfloat16 g_wqt_lo[ELEMS];
__device__ __align__(1024) __nv_bfloat16 g_wkt_hi[ELEMS];
__device__ __align__(1024) __nv_bfloat16 g_wkt_lo[ELEMS];
__device__ __align__(1024) __nv_bfloat16 g_wvt_hi[ELEMS];
__device__ __align__(1024) __nv_bfloat16 g_wvt_lo[ELEMS];
__device__ __align__(1024) __nv_bfloat16 g_q_hi[ELEMS];
__device__ __align__(1024) __nv_bfloat16 g_q_lo[ELEMS];
__device__ __align__(1024) __nv_bfloat16 g_k_hi[ELEMS];
__device__ __align__(1024) __nv_bfloat16 g_k_lo[ELEMS];
__device__ __align__(1024) __nv_bfloat16 g_v_hi[ELEMS];
__device__ __align__(1024) __nv_bfloat16 g_v_lo[ELEMS];
__device__ __align__(1024) __nv_bfloat16 g_p_hi[ELEMS];
__device__ __align__(1024) __nv_bfloat16 g_p_lo[ELEMS];
__device__ __align__(1024) float g_s[ELEMS];

__device__ __forceinline__ uint32_t smem_u32(const void* p) {
  uint32_t a;
  asm("{ .reg .u64 t; cvta.to.shared.u64 t, %1; cvt.u32.u64 %0, t; }"
      : "=r"(a) : "l"(p));
  return a;
}
__device__ __forceinline__ uint32_t pack2(__nv_bfloat16 a, __nv_bfloat16 b) {
  return (uint32_t)__bfloat16_as_ushort(a) |
         ((uint32_t)__bfloat16_as_ushort(b) << 16);
}

#define CP16(s, g) \
  asm volatile("cp.async.cg.shared.global [%0], [%1], 16;" ::"r"(s), "l"(g))
#define CP_COMMIT() asm volatile("cp.async.commit_group;")
#define CP_WAIT1() asm volatile("cp.async.wait_group 1;")
#define CP_WAIT0() asm volatile("cp.async.wait_group 0;")

#define LDSM4(r, addr)                                                       \
  asm volatile("ldmatrix.sync.aligned.m8n8.x4.shared.b16 {%0,%1,%2,%3}, [%4];" \
               : "=r"((r)[0]), "=r"((r)[1]), "=r"((r)[2]), "=r"((r)[3])      \
               : "r"(addr))

#define MMA16816(d, a, b0, b1)                                              \
  asm volatile(                                                             \
      "mma.sync.aligned.m16n8k16.row.col.f32.bf16.bf16.f32 "                \
      "{%0,%1,%2,%3},{%4,%5,%6,%7},{%8,%9},{%0,%1,%2,%3};"                  \
      : "+f"((d)[0]), "+f"((d)[1]), "+f"((d)[2]), "+f"((d)[3])              \
      : "r"((a)[0]), "r"((a)[1]), "r"((a)[2]), "r"((a)[3]), "r"(b0), "r"(b1))

// ---------------------------------------------------------------------------
// Split-bf16 GEMM: C[4096,4096] = A @ B^T, K=4096, operands hi/lo bf16 K-major.
// CTA tile 256(M) x 128(N), BK=64, 2-stage cp.async double buffer,
// 256 threads = 8 warps, each warp 64x64 (4 M-warps x 2 N-warps).
// blockIdx.z selects the B/bias/out triple (fused projections).
// EPI 0: +bias -> hi/lo bf16.  EPI 1: *SM_SCALE -> fp32.  EPI 2: fp32.
// ---------------------------------------------------------------------------
#define STB 98304          // stage bytes: Ah 32K + Al 32K + Bh 16K + Bl 16K
#define OFF_AL 32768
#define OFF_BH 65536
#define OFF_BL 81920
#define NK (DIM / 64)      // 64 k-stages

template <int EPI>
__global__ __launch_bounds__(256, 1) void gemm_mma(
    const __nv_bfloat16* __restrict__ Ah, const __nv_bfloat16* __restrict__ Al,
    const __nv_bfloat16* __restrict__ Bh0, const __nv_bfloat16* __restrict__ Bl0,
    const __nv_bfloat16* __restrict__ Bh1, const __nv_bfloat16* __restrict__ Bl1,
    const __nv_bfloat16* __restrict__ Bh2, const __nv_bfloat16* __restrict__ Bl2,
    const float* __restrict__ bias0, const float* __restrict__ bias1,
    const float* __restrict__ bias2, float* __restrict__ outF,
    __nv_bfloat16* __restrict__ oH0, __nv_bfloat16* __restrict__ oL0,
    __nv_bfloat16* __restrict__ oH1, __nv_bfloat16* __restrict__ oL1,
    __nv_bfloat16* __restrict__ oH2, __nv_bfloat16* __restrict__ oL2) {
  extern __shared__ __align__(128) char dyn[];
  const uint32_t smem = smem_u32(dyn);

  const int z = blockIdx.z;
  const __nv_bfloat16* Bh = (z == 0) ? Bh0 : (z == 1) ? Bh1 : Bh2;
  const __nv_bfloat16* Bl = (z == 0) ? Bl0 : (z == 1) ? Bl1 : Bl2;
  const float* bias = (z == 0) ? bias0 : (z == 1) ? bias1 : bias2;
  __nv_bfloat16* outH = (z == 0) ? oH0 : (z == 1) ? oH1 : oH2;
  __nv_bfloat16* outL = (z == 0) ? oL0 : (z == 1) ? oL1 : oL2;

  const int tid = threadIdx.x;
  const int lane = tid & 31;
  const int wid = tid >> 5;
  const int wm = (wid & 3) * 64;   // 4 warps down (256 M)
  const int wn = (wid >> 2) * 64;  // 2 warps across (128 N)
  const int rowBase = blockIdx.y * 256;
  const int colBase = blockIdx.x * 128;

  // ldmatrix per-lane address components
  const int mat = lane >> 3, rin = lane & 7;
  const int aRow = (mat & 1) * 8 + rin;
  const int aC = mat >> 1;
  const int bRow = (mat >> 1) * 8 + rin;
  const int bC = mat & 1;

  float acc[4][8][4];
#pragma unroll
  for (int i = 0; i < 4; i++)
#pragma unroll
    for (int j = 0; j < 8; j++)
#pragma unroll
      for (int l = 0; l < 4; l++) acc[i][j][l] = 0.0f;

  // ---- stage loader: 96KB = 6144 16B-chunks, 24 cp.async per thread ----
  auto load_stage = [&](int kt, int st) {
    const uint32_t sb = smem + st * STB;
    const int kb = kt * 128;  // byte offset along K
#pragma unroll
    for (int i = 0; i < 24; i++) {
      const int id = i * 256 + tid;
      uint32_t s;
      const char* g;
      if (i < 8) {  // Ah: 256 rows x 8 chunks
        const int r = id >> 3, c = id & 7;
        g = (const char*)Ah + (size_t)(rowBase + r) * (DIM * 2) + kb + c * 16;
        s = sb + r * 128 + ((c ^ (r & 7)) << 4);
      } else if (i < 16) {  // Al
        const int r = (id - 2048) >> 3, c = id & 7;
        g = (const char*)Al + (size_t)(rowBase + r) * (DIM * 2) + kb + c * 16;
        s = sb + OFF_AL + r * 128 + ((c ^ (r & 7)) << 4);
      } else if (i < 20) {  // Bh: 128 rows x 8 chunks
        const int r = (id - 4096) >> 3, c = id & 7;
        g = (const char*)Bh + (size_t)(colBase + r) * (DIM * 2) + kb + c * 16;
        s = sb + OFF_BH + r * 128 + ((c ^ (r & 7)) << 4);
      } else {  // Bl
        const int r = (id - 5120) >> 3, c = id & 7;
        g = (const char*)Bl + (size_t)(colBase + r) * (DIM * 2) + kb + c * 16;
        s = sb + OFF_BL + r * 128 + ((c ^ (r & 7)) << 4);
      }
      CP16(s, g);
    }
  };

  load_stage(0, 0);
  CP_COMMIT();

  for (int kt = 0; kt < NK; kt++) {
    if (kt + 1 < NK) {
      load_stage(kt + 1, (kt + 1) & 1);
      CP_COMMIT();
      CP_WAIT1();
    } else {
      CP_WAIT0();
    }
    __syncthreads();

    const uint32_t sb = smem + (kt & 1) * STB;
#pragma unroll
    for (int ks = 0; ks < 4; ks++) {
      uint32_t ah[4][4], al[4][4], bh[4][4], bl[4][4];
#pragma unroll
      for (int mi = 0; mi < 4; mi++) {
        const int row = wm + mi * 16 + aRow;
        const int c = ks * 2 + aC;
        const uint32_t ad = sb + row * 128 + ((c ^ rin) << 4);
        LDSM4(ah[mi], ad);
        LDSM4(al[mi], ad + OFF_AL);
      }
#pragma unroll
      for (int g = 0; g < 4; g++) {
        const int row = wn + g * 16 + bRow;
        const int c = ks * 2 + bC;
        const uint32_t bd = sb + OFF_BH + row * 128 + ((c ^ rin) << 4);
        LDSM4(bh[g], bd);
        LDSM4(bl[g], bd + (OFF_BL - OFF_BH));
      }
#pragma unroll
      for (int mi = 0; mi < 4; mi++)
#pragma unroll
        for (int g = 0; g < 4; g++) {
          MMA16816(acc[mi][2 * g + 0], ah[mi], bh[g][0], bh[g][1]);
          MMA16816(acc[mi][2 * g + 1], ah[mi], bh[g][2], bh[g][3]);
          MMA16816(acc[mi][2 * g + 0], ah[mi], bl[g][0], bl[g][1]);
          MMA16816(acc[mi][2 * g + 1], ah[mi], bl[g][2], bl[g][3]);
          MMA16816(acc[mi][2 * g + 0], al[mi], bh[g][0], bh[g][1]);
          MMA16816(acc[mi][2 * g + 1], al[mi], bh[g][2], bh[g][3]);
        }
    }
    __syncthreads();
  }

  // ---- epilogue ----
  const int rL = lane >> 2;
  const int cL = (lane & 3) * 2;
#pragma unroll
  for (int mi = 0; mi < 4; mi++) {
#pragma unroll
    for (int nb = 0; nb < 8; nb++) {
      const int col = colBase + wn + nb * 8 + cL;
      const int row0 = rowBase + wm + mi * 16 + rL;
      const int row1 = row0 + 8;
      const float* a = acc[mi][nb];
      if (EPI == 0) {
        const float b0v = __ldg(&bias[col]);
        const float b1v = __ldg(&bias[col + 1]);
        const float v0 = a[0] + b0v, v1 = a[1] + b1v;
        const float v2 = a[2] + b0v, v3 = a[3] + b1v;
        const __nv_bfloat16 h0 = __float2bfloat16(v0),
                            h1 = __float2bfloat16(v1);
        const __nv_bfloat16 h2 = __float2bfloat16(v2),
                            h3 = __float2bfloat16(v3);
        *reinterpret_cast<uint32_t*>(&outH[(size_t)row0 * DIM + col]) =
            pack2(h0, h1);
        *reinterpret_cast<uint32_t*>(&outH[(size_t)row1 * DIM + col]) =
            pack2(h2, h3);
        *reinterpret_cast<uint32_t*>(&outL[(size_t)row0 * DIM + col]) =
            pack2(__float2bfloat16(v0 - __bfloat162float(h0)),
                  __float2bfloat16(v1 - __bfloat162float(h1)));
        *reinterpret_cast<uint32_t*>(&outL[(size_t)row1 * DIM + col]) =
            pack2(__float2bfloat16(v2 - __bfloat162float(h2)),
                  __float2bfloat16(v3 - __bfloat162float(h3)));
      } else {
        const float s = (EPI == 1) ? SM_SCALE : 1.0f;
        *reinterpret_cast<float2*>(&outF[(size_t)row0 * DIM + col]) =
            make_float2(a[0] * s, a[1] * s);
        *reinterpret_cast<float2*>(&outF[(size_t)row1 * DIM + col]) =
            make_float2(a[2] * s, a[3] * s);
      }
    }
  }
}

// ---------------------------------------------------------------------------
// Elementwise split: fp32 -> (hi, lo) bf16.
// ---------------------------------------------------------------------------
__global__ __launch_bounds__(256) void split_plain(
    const float4* __restrict__ in, uint2* __restrict__ h,
    uint2* __restrict__ l) {
  const size_t i = (size_t)blockIdx.x * 256 + threadIdx.x;
  const float4 v = in[i];
  const __nv_bfloat16 h0 = __float2bfloat16(v.x), h1 = __float2bfloat16(v.y);
  const __nv_bfloat16 h2 = __float2bfloat16(v.z), h3 = __float2bfloat16(v.w);
  h[i] = make_uint2(pack2(h0, h1), pack2(h2, h3));
  l[i] = make_uint2(pack2(__float2bfloat16(v.x - __bfloat162float(h0)),
                          __float2bfloat16(v.y - __bfloat162float(h1))),
                    pack2(__float2bfloat16(v.z - __bfloat162float(h2)),
                          __float2bfloat16(v.w - __bfloat162float(h3))));
}

// ---------------------------------------------------------------------------
// Transpose + split: W fp32 -> Wt hi/lo bf16 (Wt[r][c] = W[c][r]).
// ---------------------------------------------------------------------------
__global__ __launch_bounds__(1024) void transpose_split(
    const float* __restrict__ W, __nv_bfloat16* __restrict__ th,
    __nv_bfloat16* __restrict__ tl) {
  __shared__ float t[32][33];
  const int bx = blockIdx.x * 32, by = blockIdx.y * 32;
  const int x = threadIdx.x & 31, y = threadIdx.x >> 5;
  t[y][x] = W[(size_t)(by + y) * DIM + bx + x];
  __syncthreads();
  const float v = t[x][y];
  const __nv_bfloat16 h = __float2bfloat16(v);
  const size_t o = (size_t)(bx + y) * DIM + by + x;
  th[o] = h;
  tl[o] = __float2bfloat16(v - __bfloat162float(h));
}

// ---------------------------------------------------------------------------
// Row softmax: fp32 scores -> p (hi, lo) bf16. 256 threads per row.
// ---------------------------------------------------------------------------
__global__ __launch_bounds__(256) void softmax_split(
    const float* __restrict__ S, __nv_bfloat16* __restrict__ ph,
    __nv_bfloat16* __restrict__ pl) {
  const int row = blockIdx.x;
  const float4* src = reinterpret_cast<const float4*>(S + (size_t)row * DIM);
  const int tid = threadIdx.x;
  float v[16];
#pragma unroll
  for (int i = 0; i < 4; i++) {
    const float4 t = src[i * 256 + tid];
    v[i * 4 + 0] = t.x; v[i * 4 + 1] = t.y;
    v[i * 4 + 2] = t.z; v[i * 4 + 3] = t.w;
  }
  float m = v[0];
#pragma unroll
  for (int i = 1; i < 16; i++) m = fmaxf(m, v[i]);
  __shared__ float red[8];
#pragma unroll
  for (int o = 16; o > 0; o >>= 1) m = fmaxf(m, __shfl_xor_sync(~0u, m, o));
  if ((tid & 31) == 0) red[tid >> 5] = m;
  __syncthreads();
  m = red[0];
#pragma unroll
  for (int w = 1; w < 8; w++) m = fmaxf(m, red[w]);

  float sum = 0.f;
#pragma unroll
  for (int i = 0; i < 16; i++) {
    v[i] = __expf(v[i] - m);
    sum += v[i];
  }
#pragma unroll
  for (int o = 16; o > 0; o >>= 1) sum += __shfl_xor_sync(~0u, sum, o);
  __syncthreads();
  if ((tid & 31) == 0) red[tid >> 5] = sum;
  __syncthreads();
  sum = 0.f;
#pragma unroll
  for (int w = 0; w < 8; w++) sum += red[w];
  const float inv = 1.0f / sum;

  uint2* hdst = reinterpret_cast<uint2*>(ph + (size_t)row * DIM);
  uint2* ldst = reinterpret_cast<uint2*>(pl + (size_t)row * DIM);
#pragma unroll
  for (int i = 0; i < 4; i++) {
    const float p0 = v[i * 4 + 0] * inv, p1 = v[i * 4 + 1] * inv;
    const float p2 = v[i * 4 + 2] * inv, p3 = v[i * 4 + 3] * inv;
    const __nv_bfloat16 h0 = __float2bfloat16(p0), h1 = __float2bfloat16(p1);
    const __nv_bfloat16 h2 = __float2bfloat16(p2), h3 = __float2bfloat16(p3);
    hdst[i * 256 + tid] = make_uint2(pack2(h0, h1), pack2(h2, h3));
    ldst[i * 256 + tid] =
        make_uint2(pack2(__float2bfloat16(p0 - __bfloat162float(h0)),
                         __float2bfloat16(p1 - __bfloat162float(h1))),
                   pack2(__float2bfloat16(p2 - __bfloat162float(h2)),
                         __float2bfloat16(p3 - __bfloat162float(h3))));
  }
}

// ---------------------------------------------------------------------------
// Launch
// ---------------------------------------------------------------------------
extern "C" void kernel_launch(void* const* d_in, const int* in_sizes, int n_in,
                              void* d_out, int out_size) {
  const float* x = (const float*)d_in[0];
  const float* Wq = (const float*)d_in[1];
  const float* bq = (const float*)d_in[2];
  const float* Wk = (const float*)d_in[3];
  const float* bk = (const float*)d_in[4];
  const float* Wv = (const float*)d_in[5];
  const float* bv = (const float*)d_in[6];
  float* out = (float*)d_out;

  void *xh, *xl, *wqh, *wql, *wkh, *wkl, *wvh, *wvl;
  void *qh, *ql, *kh, *kl, *vh, *vl, *pph, *ppl, *sf;
  cudaGetSymbolAddress(&xh, g_x_hi);    cudaGetSymbolAddress(&xl, g_x_lo);
  cudaGetSymbolAddress(&wqh, g_wqt_hi); cudaGetSymbolAddress(&wql, g_wqt_lo);
  cudaGetSymbolAddress(&wkh, g_wkt_hi); cudaGetSymbolAddress(&wkl, g_wkt_lo);
  cudaGetSymbolAddress(&wvh, g_wvt_hi); cudaGetSymbolAddress(&wvl, g_wvt_lo);
  cudaGetSymbolAddress(&qh, g_q_hi);    cudaGetSymbolAddress(&ql, g_q_lo);
  cudaGetSymbolAddress(&kh, g_k_hi);    cudaGetSymbolAddress(&kl, g_k_lo);
  cudaGetSymbolAddress(&vh, g_v_hi);    cudaGetSymbolAddress(&vl, g_v_lo);
  cudaGetSymbolAddress(&pph, g_p_hi);   cudaGetSymbolAddress(&ppl, g_p_lo);
  cudaGetSymbolAddress(&sf, g_s);

  const int dynSmem = 2 * STB;
  cudaFuncSetAttribute(gemm_mma<0>, cudaFuncAttributeMaxDynamicSharedMemorySize,
                       dynSmem);
  cudaFuncSetAttribute(gemm_mma<1>, cudaFuncAttributeMaxDynamicSharedMemorySize,
                       dynSmem);
  cudaFuncSetAttribute(gemm_mma<2>, cudaFuncAttributeMaxDynamicSharedMemorySize,
                       dynSmem);

  // 1) conversions
  split_plain<<<ELEMS / 4 / 256, 256>>>((const float4*)x, (uint2*)xh,
                                        (uint2*)xl);
  dim3 tg(DIM / 32, DIM / 32);
  transpose_split<<<tg, 1024>>>(Wq, (__nv_bfloat16*)wqh, (__nv_bfloat16*)wql);
  transpose_split<<<tg, 1024>>>(Wk, (__nv_bfloat16*)wkh, (__nv_bfloat16*)wkl);
  transpose_split<<<tg, 1024>>>(Wv, (__nv_bfloat16*)wvh, (__nv_bfloat16*)wvl);

  // 2) fused projections: z=0 -> q (hi/lo), z=1 -> k, z=2 -> v
  dim3 gp(DIM / 128, DIM / 256, 3);
  gemm_mma<0><<<gp, 256, dynSmem>>>(
      (__nv_bfloat16*)xh, (__nv_bfloat16*)xl,
      (__nv_bfloat16*)wqh, (__nv_bfloat16*)wql,
      (__nv_bfloat16*)wkh, (__nv_bfloat16*)wkl,
      (__nv_bfloat16*)wvh, (__nv_bfloat16*)wvl,
      bq, bk, bv, nullptr,
      (__nv_bfloat16*)qh, (__nv_bfloat16*)ql,
      (__nv_bfloat16*)kh, (__nv_bfloat16*)kl,
      (__nv_bfloat16*)vh, (__nv_bfloat16*)vl);

  // 3) scores = q @ k^T * scale
  dim3 gs(DIM / 128, DIM / 256, 1);
  gemm_mma<1><<<gs, 256, dynSmem>>>(
      (__nv_bfloat16*)qh, (__nv_bfloat16*)ql,
      (__nv_bfloat16*)kh, (__nv_bfloat16*)kl,
      (__nv_bfloat16*)kh, (__nv_bfloat16*)kl,
      (__nv_bfloat16*)kh, (__nv_bfloat16*)kl,
      nullptr, nullptr, nullptr, (float*)sf,
      nullptr, nullptr, nullptr, nullptr, nullptr, nullptr);

  // 4) softmax -> p hi/lo
  softmax_split<<<DIM, 256>>>((const float*)sf, (__nv_bfloat16*)pph,
                              (__nv_bfloat16*)ppl);

  // 5) out = p @ v^T
  gemm_mma<2><<<gs, 256, dynSmem>>>(
      (__nv_bfloat16*)pph, (__nv_bfloat16*)ppl,
      (__nv_bfloat16*)vh, (__nv_bfloat16*)vl,
      (__nv_bfloat16*)vh, (__nv_bfloat16*)vl,
      (__nv_bfloat16*)vh, (__nv_bfloat16*)vl,
      nullptr, nullptr, nullptr, out,
      nullptr, nullptr, nullptr, nullptr, nullptr, nullptr);
}

// round 7
// speedup vs baseline: 1.1011x; 1.1011x over previous
#include <cuda_runtime.h>
#include <cuda_bf16.h>
#include <cstdint>

#define DIM 4096
constexpr float SM_SCALE = 0.015625f;  // 1/sqrt(4096)
#define ELEMS ((size_t)DIM * (size_t)DIM)

// ---------------------------------------------------------------------------
// Scratch (__device__ globals; alloc-free rule).
// ---------------------------------------------------------------------------
__device__ __align__(1024) __nv_bfloat16 g_x_hi[ELEMS];
__device__ __align__(1024) __nv_bfloat16 g_x_lo[ELEMS];
__device__ __align__(1024) __nv_bfloat16 g_wqt_hi[ELEMS];
__device__ __align__(1024) __nv_bfloat16 g_wqt_lo[ELEMS];
__device__ __align__(1024) __nv_bfloat16 g_wkt_hi[ELEMS];
__device__ __align__(1024) __nv_bfloat16 g_wkt_lo[ELEMS];
__device__ __align__(1024) __nv_bfloat16 g_wvt_hi[ELEMS];
__device__ __align__(1024) __nv_bfloat16 g_wvt_lo[ELEMS];
__device__ __align__(1024) __nv_bfloat16 g_q_hi[ELEMS];
__device__ __align__(1024) __nv_bfloat16 g_q_lo[ELEMS];
__device__ __align__(1024) __nv_bfloat16 g_k_hi[ELEMS];
__device__ __align__(1024) __nv_bfloat16 g_k_lo[ELEMS];
__device__ __align__(1024) __nv_bfloat16 g_v_hi[ELEMS];
__device__ __align__(1024) __nv_bfloat16 g_v_lo[ELEMS];
__device__ __align__(1024) __nv_bfloat16 g_p_hi[ELEMS];
__device__ __align__(1024) __nv_bfloat16 g_p_lo[ELEMS];
__device__ __align__(1024) float g_s[ELEMS];

__device__ __forceinline__ uint32_t smem_u32(const void* p) {
  uint32_t a;
  asm("{ .reg .u64 t; cvta.to.shared.u64 t, %1; cvt.u32.u64 %0, t; }"
      : "=r"(a) : "l"(p));
  return a;
}
__device__ __forceinline__ uint32_t pack2(__nv_bfloat16 a, __nv_bfloat16 b) {
  return (uint32_t)__bfloat16_as_ushort(a) |
         ((uint32_t)__bfloat16_as_ushort(b) << 16);
}

#define CP16(s, g) \
  asm volatile("cp.async.cg.shared.global [%0], [%1], 16;" ::"r"(s), "l"(g))
#define CP_COMMIT() asm volatile("cp.async.commit_group;")
#define CP_WAIT1() asm volatile("cp.async.wait_group 1;")

#define LDSM4(r, addr)                                                       \
  asm volatile("ldmatrix.sync.aligned.m8n8.x4.shared.b16 {%0,%1,%2,%3}, [%4];" \
               : "=r"((r)[0]), "=r"((r)[1]), "=r"((r)[2]), "=r"((r)[3])      \
               : "r"(addr))

#define MMA16816(d, a, b0, b1)                                              \
  asm volatile(                                                             \
      "mma.sync.aligned.m16n8k16.row.col.f32.bf16.bf16.f32 "                \
      "{%0,%1,%2,%3},{%4,%5,%6,%7},{%8,%9},{%0,%1,%2,%3};"                  \
      : "+f"((d)[0]), "+f"((d)[1]), "+f"((d)[2]), "+f"((d)[3])              \
      : "r"((a)[0]), "r"((a)[1]), "r"((a)[2]), "r"((a)[3]), "r"(b0), "r"(b1))

// ---------------------------------------------------------------------------
// Split-bf16 GEMM: C[4096,4096] = A @ B^T, K=4096, operands hi/lo bf16
// K-major. Tile 128x128, BK=64, 3-stage cp.async, 256 threads (8 warps 32x64).
// blockIdx.z selects the B/bias/out triple (fused projections).
// EPI 0: +bias -> hi/lo bf16 out. EPI 1: *SM_SCALE -> fp32. EPI 2: fp32.
// ---------------------------------------------------------------------------
#define NSTAGE 3
#define STB (64 * 1024)   // stage bytes: 4 operand tiles x 16KB
#define OPB (16 * 1024)   // one 128x64 bf16 tile
#define NK (DIM / 64)     // 64 k-stages

template <int EPI>
__global__ __launch_bounds__(256, 1) void gemm_mma(
    const __nv_bfloat16* __restrict__ Ah, const __nv_bfloat16* __restrict__ Al,
    const __nv_bfloat16* __restrict__ Bh0, const __nv_bfloat16* __restrict__ Bl0,
    const __nv_bfloat16* __restrict__ Bh1, const __nv_bfloat16* __restrict__ Bl1,
    const __nv_bfloat16* __restrict__ Bh2, const __nv_bfloat16* __restrict__ Bl2,
    const float* __restrict__ bias0, const float* __restrict__ bias1,
    const float* __restrict__ bias2, float* __restrict__ outF,
    __nv_bfloat16* __restrict__ oH0, __nv_bfloat16* __restrict__ oL0,
    __nv_bfloat16* __restrict__ oH1, __nv_bfloat16* __restrict__ oL1,
    __nv_bfloat16* __restrict__ oH2, __nv_bfloat16* __restrict__ oL2) {
  extern __shared__ __align__(128) char dyn[];
  const uint32_t smem = smem_u32(dyn);

  const int z = blockIdx.z;
  const __nv_bfloat16* Bh = (z == 0) ? Bh0 : (z == 1) ? Bh1 : Bh2;
  const __nv_bfloat16* Bl = (z == 0) ? Bl0 : (z == 1) ? Bl1 : Bl2;
  const float* bias = (z == 0) ? bias0 : (z == 1) ? bias1 : bias2;
  __nv_bfloat16* outH = (z == 0) ? oH0 : (z == 1) ? oH1 : oH2;
  __nv_bfloat16* outL = (z == 0) ? oL0 : (z == 1) ? oL1 : oL2;

  const int tid = threadIdx.x;
  const int lane = tid & 31;
  const int wid = tid >> 5;
  const int wm = (wid & 3) * 32;   // warp M offset (4 warps down)
  const int wn = (wid >> 2) * 64;  // warp N offset (2 warps across)
  const int rowBase = blockIdx.y * 128;
  const int colBase = blockIdx.x * 128;

  // ldmatrix per-lane address components
  const int mat = lane >> 3, rin = lane & 7;
  const int aRow = (mat & 1) * 8 + rin;
  const int aC = mat >> 1;
  const int bRow = (mat >> 1) * 8 + rin;
  const int bC = mat & 1;

  float acc[2][8][4];
#pragma unroll
  for (int i = 0; i < 2; i++)
#pragma unroll
    for (int j = 0; j < 8; j++)
#pragma unroll
      for (int l = 0; l < 4; l++) acc[i][j][l] = 0.0f;

  // ---- stage loader: 4 tiles x 1024 16B-chunks, 16 cp.async per thread ----
  auto load_stage = [&](int kt, int st) {
    const uint32_t sb = smem + st * STB;
#pragma unroll
    for (int i = 0; i < 16; i++) {
      const int id = i * 256 + tid;
      const int o = id >> 10;
      const int r = (id >> 3) & 127;
      const int c = id & 7;
      const __nv_bfloat16* gb =
          (o == 0) ? Ah : (o == 1) ? Al : (o == 2) ? Bh : Bl;
      const int gRow = ((o < 2) ? rowBase : colBase) + r;
      const char* g =
          (const char*)gb + (size_t)gRow * (DIM * 2) + kt * 128 + c * 16;
      const uint32_t s = sb + o * OPB + r * 128 + ((c ^ (r & 7)) << 4);
      CP16(s, g);
    }
  };

  // prologue: 2 stages in flight
  load_stage(0, 0);
  CP_COMMIT();
  load_stage(1, 1);
  CP_COMMIT();

  for (int kt = 0; kt < NK; kt++) {
    CP_WAIT1();
    __syncthreads();
    // issue next-next stage (slot freed by last iteration's consumers)
    if (kt + 2 < NK) load_stage(kt + 2, (kt + 2) % NSTAGE);
    CP_COMMIT();

    const uint32_t sb = smem + (kt % NSTAGE) * STB;
    const uint32_t sAh = sb;
    const uint32_t sBh = sb + 2 * OPB;
#pragma unroll
    for (int ks = 0; ks < 4; ks++) {
      uint32_t ah[2][4], al[2][4], bh[4][4], bl[4][4];
#pragma unroll
      for (int mi = 0; mi < 2; mi++) {
        const int row = wm + mi * 16 + aRow;
        const int c = ks * 2 + aC;
        const uint32_t ad = sAh + row * 128 + ((c ^ rin) << 4);
        LDSM4(ah[mi], ad);
        LDSM4(al[mi], ad + OPB);
      }
#pragma unroll
      for (int g = 0; g < 4; g++) {
        const int row = wn + g * 16 + bRow;
        const int c = ks * 2 + bC;
        const uint32_t bd = sBh + row * 128 + ((c ^ rin) << 4);
        LDSM4(bh[g], bd);
        LDSM4(bl[g], bd + OPB);
      }
#pragma unroll
      for (int mi = 0; mi < 2; mi++)
#pragma unroll
        for (int g = 0; g < 4; g++) {
          MMA16816(acc[mi][2 * g + 0], ah[mi], bh[g][0], bh[g][1]);
          MMA16816(acc[mi][2 * g + 1], ah[mi], bh[g][2], bh[g][3]);
          MMA16816(acc[mi][2 * g + 0], ah[mi], bl[g][0], bl[g][1]);
          MMA16816(acc[mi][2 * g + 1], ah[mi], bl[g][2], bl[g][3]);
          MMA16816(acc[mi][2 * g + 0], al[mi], bh[g][0], bh[g][1]);
          MMA16816(acc[mi][2 * g + 1], al[mi], bh[g][2], bh[g][3]);
        }
    }
  }

  // ---- epilogue ----
  const int r0b = rowBase + wm + (lane >> 2);
  const int c0b = colBase + wn + (lane & 3) * 2;
#pragma unroll
  for (int mi = 0; mi < 2; mi++) {
#pragma unroll
    for (int nb = 0; nb < 8; nb++) {
      const int col = c0b + nb * 8;
      const int row0 = r0b + mi * 16;
      const int row1 = row0 + 8;
      const float* a = acc[mi][nb];
      if (EPI == 0) {
        const float b0v = __ldg(&bias[col]);
        const float b1v = __ldg(&bias[col + 1]);
        const float v0 = a[0] + b0v, v1 = a[1] + b1v;
        const float v2 = a[2] + b0v, v3 = a[3] + b1v;
        const __nv_bfloat16 h0 = __float2bfloat16(v0),
                            h1 = __float2bfloat16(v1);
        const __nv_bfloat16 h2 = __float2bfloat16(v2),
                            h3 = __float2bfloat16(v3);
        *reinterpret_cast<uint32_t*>(&outH[(size_t)row0 * DIM + col]) =
            pack2(h0, h1);
        *reinterpret_cast<uint32_t*>(&outH[(size_t)row1 * DIM + col]) =
            pack2(h2, h3);
        *reinterpret_cast<uint32_t*>(&outL[(size_t)row0 * DIM + col]) =
            pack2(__float2bfloat16(v0 - __bfloat162float(h0)),
                  __float2bfloat16(v1 - __bfloat162float(h1)));
        *reinterpret_cast<uint32_t*>(&outL[(size_t)row1 * DIM + col]) =
            pack2(__float2bfloat16(v2 - __bfloat162float(h2)),
                  __float2bfloat16(v3 - __bfloat162float(h3)));
      } else {
        const float s = (EPI == 1) ? SM_SCALE : 1.0f;
        *reinterpret_cast<float2*>(&outF[(size_t)row0 * DIM + col]) =
            make_float2(a[0] * s, a[1] * s);
        *reinterpret_cast<float2*>(&outF[(size_t)row1 * DIM + col]) =
            make_float2(a[2] * s, a[3] * s);
      }
    }
  }
}

// ---------------------------------------------------------------------------
// Elementwise split: fp32 -> (hi, lo) bf16.
// ---------------------------------------------------------------------------
__global__ __launch_bounds__(256) void split_plain(
    const float4* __restrict__ in, uint2* __restrict__ h,
    uint2* __restrict__ l) {
  const size_t i = (size_t)blockIdx.x * 256 + threadIdx.x;
  const float4 v = in[i];
  const __nv_bfloat16 h0 = __float2bfloat16(v.x), h1 = __float2bfloat16(v.y);
  const __nv_bfloat16 h2 = __float2bfloat16(v.z), h3 = __float2bfloat16(v.w);
  h[i] = make_uint2(pack2(h0, h1), pack2(h2, h3));
  l[i] = make_uint2(pack2(__float2bfloat16(v.x - __bfloat162float(h0)),
                          __float2bfloat16(v.y - __bfloat162float(h1))),
                    pack2(__float2bfloat16(v.z - __bfloat162float(h2)),
                          __float2bfloat16(v.w - __bfloat162float(h3))));
}

// ---------------------------------------------------------------------------
// Transpose + split (vectorized): W fp32 -> Wt hi/lo bf16, Wt[r][c]=W[c][r].
// 64x64 tile, 256 threads, float4 loads, uint2 bf16 stores.
// ---------------------------------------------------------------------------
__global__ __launch_bounds__(256) void transpose_split(
    const float* __restrict__ W, __nv_bfloat16* __restrict__ th,
    __nv_bfloat16* __restrict__ tl) {
  __shared__ float t[64][65];
  const int bx = blockIdx.x * 64, by = blockIdx.y * 64;
  const int tid = threadIdx.x;
  const int lr = tid >> 4;
  const int lc = (tid & 15) * 4;
#pragma unroll
  for (int i = 0; i < 4; i++) {
    const int r = lr + i * 16;
    const float4 v =
        *reinterpret_cast<const float4*>(&W[(size_t)(by + r) * DIM + bx + lc]);
    t[r][lc] = v.x;
    t[r][lc + 1] = v.y;
    t[r][lc + 2] = v.z;
    t[r][lc + 3] = v.w;
  }
  __syncthreads();
#pragma unroll
  for (int i = 0; i < 4; i++) {
    const int orow = lr + i * 16;  // output row = original column
    const float v0 = t[lc + 0][orow], v1 = t[lc + 1][orow];
    const float v2 = t[lc + 2][orow], v3 = t[lc + 3][orow];
    const __nv_bfloat16 h0 = __float2bfloat16(v0), h1 = __float2bfloat16(v1);
    const __nv_bfloat16 h2 = __float2bfloat16(v2), h3 = __float2bfloat16(v3);
    const size_t o = (size_t)(bx + orow) * DIM + by + lc;
    *reinterpret_cast<uint2*>(&th[o]) =
        make_uint2(pack2(h0, h1), pack2(h2, h3));
    *reinterpret_cast<uint2*>(&tl[o]) =
        make_uint2(pack2(__float2bfloat16(v0 - __bfloat162float(h0)),
                         __float2bfloat16(v1 - __bfloat162float(h1))),
                   pack2(__float2bfloat16(v2 - __bfloat162float(h2)),
                         __float2bfloat16(v3 - __bfloat162float(h3))));
  }
}

// ---------------------------------------------------------------------------
// Row softmax: fp32 scores -> p (hi, lo) bf16. 256 threads per row.
// ---------------------------------------------------------------------------
__global__ __launch_bounds__(256) void softmax_split(
    const float* __restrict__ S, __nv_bfloat16* __restrict__ ph,
    __nv_bfloat16* __restrict__ pl) {
  const int row = blockIdx.x;
  const float4* src = reinterpret_cast<const float4*>(S + (size_t)row * DIM);
  const int tid = threadIdx.x;
  float v[16];
#pragma unroll
  for (int i = 0; i < 4; i++) {
    const float4 t = src[i * 256 + tid];
    v[i * 4 + 0] = t.x; v[i * 4 + 1] = t.y;
    v[i * 4 + 2] = t.z; v[i * 4 + 3] = t.w;
  }
  float m = v[0];
#pragma unroll
  for (int i = 1; i < 16; i++) m = fmaxf(m, v[i]);
  __shared__ float red[8];
#pragma unroll
  for (int o = 16; o > 0; o >>= 1) m = fmaxf(m, __shfl_xor_sync(~0u, m, o));
  if ((tid & 31) == 0) red[tid >> 5] = m;
  __syncthreads();
  m = red[0];
#pragma unroll
  for (int w = 1; w < 8; w++) m = fmaxf(m, red[w]);

  float sum = 0.f;
#pragma unroll
  for (int i = 0; i < 16; i++) {
    v[i] = __expf(v[i] - m);
    sum += v[i];
  }
#pragma unroll
  for (int o = 16; o > 0; o >>= 1) sum += __shfl_xor_sync(~0u, sum, o);
  __syncthreads();
  if ((tid & 31) == 0) red[tid >> 5] = sum;
  __syncthreads();
  sum = 0.f;
#pragma unroll
  for (int w = 0; w < 8; w++) sum += red[w];
  const float inv = 1.0f / sum;

  uint2* hdst = reinterpret_cast<uint2*>(ph + (size_t)row * DIM);
  uint2* ldst = reinterpret_cast<uint2*>(pl + (size_t)row * DIM);
#pragma unroll
  for (int i = 0; i < 4; i++) {
    const float p0 = v[i * 4 + 0] * inv, p1 = v[i * 4 + 1] * inv;
    const float p2 = v[i * 4 + 2] * inv, p3 = v[i * 4 + 3] * inv;
    const __nv_bfloat16 h0 = __float2bfloat16(p0), h1 = __float2bfloat16(p1);
    const __nv_bfloat16 h2 = __float2bfloat16(p2), h3 = __float2bfloat16(p3);
    hdst[i * 256 + tid] = make_uint2(pack2(h0, h1), pack2(h2, h3));
    ldst[i * 256 + tid] =
        make_uint2(pack2(__float2bfloat16(p0 - __bfloat162float(h0)),
                         __float2bfloat16(p1 - __bfloat162float(h1))),
                   pack2(__float2bfloat16(p2 - __bfloat162float(h2)),
                         __float2bfloat16(p3 - __bfloat162float(h3))));
  }
}

// ---------------------------------------------------------------------------
// Launch
// ---------------------------------------------------------------------------
extern "C" void kernel_launch(void* const* d_in, const int* in_sizes, int n_in,
                              void* d_out, int out_size) {
  const float* x = (const float*)d_in[0];
  const float* Wq = (const float*)d_in[1];
  const float* bq = (const float*)d_in[2];
  const float* Wk = (const float*)d_in[3];
  const float* bk = (const float*)d_in[4];
  const float* Wv = (const float*)d_in[5];
  const float* bv = (const float*)d_in[6];
  float* out = (float*)d_out;

  void *xh, *xl, *wqh, *wql, *wkh, *wkl, *wvh, *wvl;
  void *qh, *ql, *kh, *kl, *vh, *vl, *pph, *ppl, *sf;
  cudaGetSymbolAddress(&xh, g_x_hi);    cudaGetSymbolAddress(&xl, g_x_lo);
  cudaGetSymbolAddress(&wqh, g_wqt_hi); cudaGetSymbolAddress(&wql, g_wqt_lo);
  cudaGetSymbolAddress(&wkh, g_wkt_hi); cudaGetSymbolAddress(&wkl, g_wkt_lo);
  cudaGetSymbolAddress(&wvh, g_wvt_hi); cudaGetSymbolAddress(&wvl, g_wvt_lo);
  cudaGetSymbolAddress(&qh, g_q_hi);    cudaGetSymbolAddress(&ql, g_q_lo);
  cudaGetSymbolAddress(&kh, g_k_hi);    cudaGetSymbolAddress(&kl, g_k_lo);
  cudaGetSymbolAddress(&vh, g_v_hi);    cudaGetSymbolAddress(&vl, g_v_lo);
  cudaGetSymbolAddress(&pph, g_p_hi);   cudaGetSymbolAddress(&ppl, g_p_lo);
  cudaGetSymbolAddress(&sf, g_s);

  const int dynSmem = NSTAGE * STB;
  cudaFuncSetAttribute(gemm_mma<0>, cudaFuncAttributeMaxDynamicSharedMemorySize,
                       dynSmem);
  cudaFuncSetAttribute(gemm_mma<1>, cudaFuncAttributeMaxDynamicSharedMemorySize,
                       dynSmem);
  cudaFuncSetAttribute(gemm_mma<2>, cudaFuncAttributeMaxDynamicSharedMemorySize,
                       dynSmem);

  // 1) conversions
  split_plain<<<ELEMS / 4 / 256, 256>>>((const float4*)x, (uint2*)xh,
                                        (uint2*)xl);
  dim3 tg(DIM / 64, DIM / 64);
  transpose_split<<<tg, 256>>>(Wq, (__nv_bfloat16*)wqh, (__nv_bfloat16*)wql);
  transpose_split<<<tg, 256>>>(Wk, (__nv_bfloat16*)wkh, (__nv_bfloat16*)wkl);
  transpose_split<<<tg, 256>>>(Wv, (__nv_bfloat16*)wvh, (__nv_bfloat16*)wvl);

  // 2) fused projections: z=0 -> q, z=1 -> k, z=2 -> v  (hi/lo outputs)
  dim3 gp(DIM / 128, DIM / 128, 3);
  gemm_mma<0><<<gp, 256, dynSmem>>>(
      (__nv_bfloat16*)xh, (__nv_bfloat16*)xl,
      (__nv_bfloat16*)wqh, (__nv_bfloat16*)wql,
      (__nv_bfloat16*)wkh, (__nv_bfloat16*)wkl,
      (__nv_bfloat16*)wvh, (__nv_bfloat16*)wvl,
      bq, bk, bv, nullptr,
      (__nv_bfloat16*)qh, (__nv_bfloat16*)ql,
      (__nv_bfloat16*)kh, (__nv_bfloat16*)kl,
      (__nv_bfloat16*)vh, (__nv_bfloat16*)vl);

  // 3) scores = q @ k^T * scale
  dim3 gs(DIM / 128, DIM / 128, 1);
  gemm_mma<1><<<gs, 256, dynSmem>>>(
      (__nv_bfloat16*)qh, (__nv_bfloat16*)ql,
      (__nv_bfloat16*)kh, (__nv_bfloat16*)kl,
      (__nv_bfloat16*)kh, (__nv_bfloat16*)kl,
      (__nv_bfloat16*)kh, (__nv_bfloat16*)kl,
      nullptr, nullptr, nullptr, (float*)sf,
      nullptr, nullptr, nullptr, nullptr, nullptr, nullptr);

  // 4) softmax -> p hi/lo
  softmax_split<<<DIM, 256>>>((const float*)sf, (__nv_bfloat16*)pph,
                              (__nv_bfloat16*)ppl);

  // 5) out = p @ v^T
  gemm_mma<2><<<gs, 256, dynSmem>>>(
      (__nv_bfloat16*)pph, (__nv_bfloat16*)ppl,
      (__nv_bfloat16*)vh, (__nv_bfloat16*)vl,
      (__nv_bfloat16*)vh, (__nv_bfloat16*)vl,
      (__nv_bfloat16*)vh, (__nv_bfloat16*)vl,
      nullptr, nullptr, nullptr, out,
      nullptr, nullptr, nullptr, nullptr, nullptr, nullptr);
}